// round 1
// baseline (speedup 1.0000x reference)
#include <cuda_runtime.h>
#include <cstdint>
#include <cstddef>

// Problem constants
#define BN_ 4
#define TN_ 2048
#define SN_ 2048
#define EN_ 512
#define HN_ 8
#define DH_ 64
#define MPROJ (BN_ * TN_)              // 8192
#define OUT0_ELEMS ((size_t)BN_ * TN_ * EN_)                 // 4,194,304
#define P_ELEMS    ((size_t)BN_ * HN_ * TN_ * SN_)           // 134,217,728

// Scratch (no cudaMalloc allowed) — device globals
__device__ float g_Q[(size_t)MPROJ * EN_];
__device__ float g_K[(size_t)MPROJ * EN_];
__device__ float g_V[(size_t)MPROJ * EN_];
__device__ float g_CTX[(size_t)MPROJ * EN_];
__device__ float g_P[P_ELEMS];   // fallback if d_out doesn't hold attn_weights

// ---------------------------------------------------------------------------
// Generic fp32 GEMM with bias + scale:  C[M,N] = (A[M,K] @ W[K,N] + b) * scale
// Tiles: 64x64x16, 256 threads, 4x4 microtile per thread.
// ---------------------------------------------------------------------------
__global__ __launch_bounds__(256) void gemm_bias_kernel(
    const float* __restrict__ A, const float* __restrict__ W,
    const float* __restrict__ bias, float* __restrict__ C,
    int M, int N, int K, float scale)
{
    const int BM = 64, BN = 64, BK = 16;
    __shared__ float As[BK][BM];   // transposed A tile: As[k][m]
    __shared__ float Bs[BK][BN];   // Bs[k][n]

    int tid = threadIdx.x;
    int tx = tid & 15, ty = tid >> 4;
    int bm = blockIdx.y * BM, bn = blockIdx.x * BN;

    float acc[4][4] = {};

    for (int k0 = 0; k0 < K; k0 += BK) {
        // Load A tile (64 rows x 16 cols), store transposed
        {
            int r = tid >> 2;            // 0..63
            int c = (tid & 3) * 4;       // 0,4,8,12
            float4 v = *(const float4*)&A[(size_t)(bm + r) * K + k0 + c];
            As[c + 0][r] = v.x; As[c + 1][r] = v.y;
            As[c + 2][r] = v.z; As[c + 3][r] = v.w;
        }
        // Load B tile (16 rows x 64 cols)
        {
            int r = tid >> 4;            // 0..15
            int c = (tid & 15) * 4;      // 0..60
            *(float4*)&Bs[r][c] = *(const float4*)&W[(size_t)(k0 + r) * N + bn + c];
        }
        __syncthreads();

#pragma unroll
        for (int k = 0; k < BK; k++) {
            float4 a4 = *(float4*)&As[k][ty * 4];
            float4 b4 = *(float4*)&Bs[k][tx * 4];
            float av[4] = {a4.x, a4.y, a4.z, a4.w};
            float bv[4] = {b4.x, b4.y, b4.z, b4.w};
#pragma unroll
            for (int i = 0; i < 4; i++)
#pragma unroll
                for (int j = 0; j < 4; j++)
                    acc[i][j] += av[i] * bv[j];
        }
        __syncthreads();
    }

#pragma unroll
    for (int i = 0; i < 4; i++) {
        int row = bm + ty * 4 + i;
#pragma unroll
        for (int j = 0; j < 4; j++) {
            int col = bn + tx * 4 + j;
            C[(size_t)row * N + col] = (acc[i][j] + bias[col]) * scale;
        }
    }
}

// ---------------------------------------------------------------------------
// Scores: per (b,h), S_tile[64 t x 64 s] = Q_h[64,64] @ K_h[64,64]^T, + masks
// grid = (S/64, T/64, B*H), 256 threads
// ---------------------------------------------------------------------------
__global__ __launch_bounds__(256) void scores_kernel(
    const float* __restrict__ Q, const float* __restrict__ Kp,
    const unsigned char* __restrict__ attn_mask,
    const unsigned char* __restrict__ kpm,
    float* __restrict__ P)
{
    __shared__ float Qs[DH_][64];   // [d][t]
    __shared__ float Ks[DH_][64];   // [d][s]

    int bh = blockIdx.z;
    int b = bh >> 3;
    int h = bh & 7;
    int t0 = blockIdx.y * 64;
    int s0 = blockIdx.x * 64;
    int tid = threadIdx.x;
    int tx = tid & 15, ty = tid >> 4;

    const float* Qbase = Q + (size_t)b * TN_ * EN_ + (size_t)h * DH_;
    const float* Kbase = Kp + (size_t)b * SN_ * EN_ + (size_t)h * DH_;

    // Load 64x64 Q and K tiles, transposed into [d][row]
#pragma unroll
    for (int it = 0; it < 4; it++) {
        int r = (tid >> 4) + it * 16;   // 0..63
        int c = (tid & 15) * 4;         // 0..60 (d index)
        float4 q = *(const float4*)&Qbase[(size_t)(t0 + r) * EN_ + c];
        Qs[c + 0][r] = q.x; Qs[c + 1][r] = q.y;
        Qs[c + 2][r] = q.z; Qs[c + 3][r] = q.w;
        float4 k = *(const float4*)&Kbase[(size_t)(s0 + r) * EN_ + c];
        Ks[c + 0][r] = k.x; Ks[c + 1][r] = k.y;
        Ks[c + 2][r] = k.z; Ks[c + 3][r] = k.w;
    }
    __syncthreads();

    float acc[4][4] = {};
#pragma unroll
    for (int k = 0; k < DH_; k++) {
        float4 a4 = *(float4*)&Qs[k][ty * 4];
        float4 b4 = *(float4*)&Ks[k][tx * 4];
        float av[4] = {a4.x, a4.y, a4.z, a4.w};
        float bv[4] = {b4.x, b4.y, b4.z, b4.w};
#pragma unroll
        for (int i = 0; i < 4; i++)
#pragma unroll
            for (int j = 0; j < 4; j++)
                acc[i][j] += av[i] * bv[j];
    }

    float* Pbase = P + (size_t)bh * TN_ * SN_;
#pragma unroll
    for (int i = 0; i < 4; i++) {
        int t = t0 + ty * 4 + i;
#pragma unroll
        for (int j = 0; j < 4; j++) {
            int s = s0 + tx * 4 + j;
            float v = acc[i][j];
            if (attn_mask[(size_t)t * SN_ + s] | kpm[(size_t)b * SN_ + s])
                v = -1e30f;
            Pbase[(size_t)t * SN_ + s] = v;
        }
    }
}

// ---------------------------------------------------------------------------
// Softmax over rows of P. One block (256 threads) per row of 2048 elements.
// ---------------------------------------------------------------------------
__global__ __launch_bounds__(256) void softmax_kernel(float* __restrict__ P)
{
    size_t row = blockIdx.x;
    float* p = P + row * (size_t)SN_;
    int tid = threadIdx.x;
    int lane = tid & 31, wid = tid >> 5;

    float4 v0 = *(float4*)&p[tid * 8];
    float4 v1 = *(float4*)&p[tid * 8 + 4];
    float vals[8] = {v0.x, v0.y, v0.z, v0.w, v1.x, v1.y, v1.z, v1.w};

    __shared__ float sm[8];

    // max reduce
    float mx = vals[0];
#pragma unroll
    for (int i = 1; i < 8; i++) mx = fmaxf(mx, vals[i]);
#pragma unroll
    for (int o = 16; o > 0; o >>= 1)
        mx = fmaxf(mx, __shfl_xor_sync(0xFFFFFFFFu, mx, o));
    if (lane == 0) sm[wid] = mx;
    __syncthreads();
    float rmax = sm[0];
#pragma unroll
    for (int i = 1; i < 8; i++) rmax = fmaxf(rmax, sm[i]);
    __syncthreads();

    // exp + sum reduce
    float s = 0.f;
#pragma unroll
    for (int i = 0; i < 8; i++) {
        vals[i] = __expf(vals[i] - rmax);
        s += vals[i];
    }
#pragma unroll
    for (int o = 16; o > 0; o >>= 1)
        s += __shfl_xor_sync(0xFFFFFFFFu, s, o);
    if (lane == 0) sm[wid] = s;
    __syncthreads();
    float rsum = 0.f;
#pragma unroll
    for (int i = 0; i < 8; i++) rsum += sm[i];
    float inv = 1.0f / rsum;

    float4 o0 = make_float4(vals[0] * inv, vals[1] * inv, vals[2] * inv, vals[3] * inv);
    float4 o1 = make_float4(vals[4] * inv, vals[5] * inv, vals[6] * inv, vals[7] * inv);
    *(float4*)&p[tid * 8] = o0;
    *(float4*)&p[tid * 8 + 4] = o1;
}

// ---------------------------------------------------------------------------
// PV: per (b,h), Ctx_tile[64 t x 64 d] = P[64, 2048] @ V_h[2048, 64]
// grid = (T/64, B*H), 256 threads, BK=16
// ---------------------------------------------------------------------------
__global__ __launch_bounds__(256) void pv_kernel(
    const float* __restrict__ P, const float* __restrict__ V,
    float* __restrict__ Ctx)
{
    const int BK = 16;
    __shared__ float Ps[BK][64];   // [s][t]
    __shared__ float Vs[BK][64];   // [s][d]

    int bh = blockIdx.y;
    int b = bh >> 3;
    int h = bh & 7;
    int t0 = blockIdx.x * 64;
    int tid = threadIdx.x;
    int tx = tid & 15, ty = tid >> 4;

    const float* Pbase = P + ((size_t)bh * TN_ + t0) * SN_;
    const float* Vbase = V + (size_t)b * SN_ * EN_ + (size_t)h * DH_;

    float acc[4][4] = {};

    for (int k0 = 0; k0 < SN_; k0 += BK) {
        {
            int r = tid >> 2;          // t row 0..63
            int c = (tid & 3) * 4;     // s col 0,4,8,12
            float4 v = *(const float4*)&Pbase[(size_t)r * SN_ + k0 + c];
            Ps[c + 0][r] = v.x; Ps[c + 1][r] = v.y;
            Ps[c + 2][r] = v.z; Ps[c + 3][r] = v.w;
        }
        {
            int r = tid >> 4;          // s row 0..15
            int c = (tid & 15) * 4;    // d col
            *(float4*)&Vs[r][c] = *(const float4*)&Vbase[(size_t)(k0 + r) * EN_ + c];
        }
        __syncthreads();

#pragma unroll
        for (int k = 0; k < BK; k++) {
            float4 a4 = *(float4*)&Ps[k][ty * 4];
            float4 b4 = *(float4*)&Vs[k][tx * 4];
            float av[4] = {a4.x, a4.y, a4.z, a4.w};
            float bv[4] = {b4.x, b4.y, b4.z, b4.w};
#pragma unroll
            for (int i = 0; i < 4; i++)
#pragma unroll
                for (int j = 0; j < 4; j++)
                    acc[i][j] += av[i] * bv[j];
        }
        __syncthreads();
    }

#pragma unroll
    for (int i = 0; i < 4; i++) {
        int t = t0 + ty * 4 + i;
#pragma unroll
        for (int j = 0; j < 4; j++) {
            int d = tx * 4 + j;
            Ctx[(size_t)b * TN_ * EN_ + (size_t)t * EN_ + (size_t)h * DH_ + d] = acc[i][j];
        }
    }
}

// ---------------------------------------------------------------------------
extern "C" void kernel_launch(void* const* d_in, const int* in_sizes, int n_in,
                              void* d_out, int out_size)
{
    const float* query = (const float*)d_in[0];
    const float* key   = (const float*)d_in[1];
    const float* value = (const float*)d_in[2];
    const unsigned char* kpm       = (const unsigned char*)d_in[3];
    const unsigned char* attn_mask = (const unsigned char*)d_in[4];
    const float* Wq = (const float*)d_in[5];
    const float* bq = (const float*)d_in[6];
    const float* Wk = (const float*)d_in[7];
    const float* bk = (const float*)d_in[8];
    const float* Wv = (const float*)d_in[9];
    const float* bv = (const float*)d_in[10];
    const float* Wo = (const float*)d_in[11];
    const float* bo = (const float*)d_in[12];

    float* out = (float*)d_out;

    float *Qp, *Kp, *Vp, *Ctx, *Pfb;
    cudaGetSymbolAddress((void**)&Qp,  g_Q);
    cudaGetSymbolAddress((void**)&Kp,  g_K);
    cudaGetSymbolAddress((void**)&Vp,  g_V);
    cudaGetSymbolAddress((void**)&Ctx, g_CTX);
    cudaGetSymbolAddress((void**)&Pfb, g_P);

    // attn_weights destination: tail of d_out if present, else device scratch
    float* P = ((size_t)out_size >= OUT0_ELEMS + P_ELEMS) ? (out + OUT0_ELEMS) : Pfb;

    dim3 blk(256);
    dim3 gProj(EN_ / 64, MPROJ / 64);   // (8, 128)

    const float scaling = 0.125f;       // HEAD_DIM^-0.5

    gemm_bias_kernel<<<gProj, blk>>>(query, Wq, bq, Qp, MPROJ, EN_, EN_, scaling);
    gemm_bias_kernel<<<gProj, blk>>>(key,   Wk, bk, Kp, MPROJ, EN_, EN_, 1.0f);
    gemm_bias_kernel<<<gProj, blk>>>(value, Wv, bv, Vp, MPROJ, EN_, EN_, 1.0f);

    dim3 gScores(SN_ / 64, TN_ / 64, BN_ * HN_);   // (32, 32, 32)
    scores_kernel<<<gScores, blk>>>(Qp, Kp, attn_mask, kpm, P);

    softmax_kernel<<<(unsigned)((size_t)BN_ * HN_ * TN_), blk>>>(P);

    dim3 gPV(TN_ / 64, BN_ * HN_);                 // (32, 32)
    pv_kernel<<<gPV, blk>>>(P, Vp, Ctx);

    gemm_bias_kernel<<<gProj, blk>>>(Ctx, Wo, bo, out, MPROJ, EN_, EN_, 1.0f);
}

// round 2
// speedup vs baseline: 1.2492x; 1.2492x over previous
#include <cuda_runtime.h>
#include <cstdint>
#include <cstddef>

#define BN_ 4
#define TN_ 2048
#define SN_ 2048
#define EN_ 512
#define HN_ 8
#define DH_ 64
#define MPROJ (BN_ * TN_)
#define OUT0_ELEMS ((size_t)BN_ * TN_ * EN_)
#define P_ELEMS    ((size_t)BN_ * HN_ * TN_ * SN_)

__device__ float g_Q[(size_t)MPROJ * EN_];
__device__ float g_K[(size_t)MPROJ * EN_];
__device__ float g_V[(size_t)MPROJ * EN_];
__device__ float g_CTX[(size_t)MPROJ * EN_];
__device__ float g_P[P_ELEMS];

// ---------------------------------------------------------------------------
// Projection GEMM: C[M,N] = (A[M,K] @ W[K,N] + b) * scale
// 128x128 tile, BK=16, 256 threads, 8x8 microtile (2x2 of 4x4).
// ---------------------------------------------------------------------------
__global__ __launch_bounds__(256) void gemm_bias_kernel(
    const float* __restrict__ A, const float* __restrict__ W,
    const float* __restrict__ bias, float* __restrict__ C,
    int M, int N, int K, float scale)
{
    const int BK = 16;
    __shared__ float As[BK * 128];   // [k][m]
    __shared__ float Bs[BK * 128];   // [k][n]

    int tid = threadIdx.x;
    int tx = tid & 15, ty = tid >> 4;
    int bm = blockIdx.y * 128, bn = blockIdx.x * 128;

    float acc[8][8] = {};

    for (int k0 = 0; k0 < K; k0 += BK) {
        // A tile: 128 rows x 16 k, store transposed As[k][m]
#pragma unroll
        for (int i = 0; i < 2; i++) {
            int f = tid + i * 256;
            int r = f >> 2;            // 0..127
            int c = (f & 3) * 4;       // 0,4,8,12
            float4 v = *(const float4*)&A[(size_t)(bm + r) * K + k0 + c];
            As[(c + 0) * 128 + r] = v.x; As[(c + 1) * 128 + r] = v.y;
            As[(c + 2) * 128 + r] = v.z; As[(c + 3) * 128 + r] = v.w;
        }
        // B tile: 16 k x 128 n
#pragma unroll
        for (int i = 0; i < 2; i++) {
            int f = tid + i * 256;
            int r = f >> 5;            // 0..15
            int c = (f & 31) * 4;      // 0..124
            *(float4*)&Bs[r * 128 + c] = *(const float4*)&W[(size_t)(k0 + r) * N + bn + c];
        }
        __syncthreads();

#pragma unroll 4
        for (int k = 0; k < BK; k++) {
            float4 a0 = *(float4*)&As[k * 128 + ty * 4];
            float4 a1 = *(float4*)&As[k * 128 + 64 + ty * 4];
            float4 b0 = *(float4*)&Bs[k * 128 + tx * 4];
            float4 b1 = *(float4*)&Bs[k * 128 + 64 + tx * 4];
            float av[8] = {a0.x, a0.y, a0.z, a0.w, a1.x, a1.y, a1.z, a1.w};
            float bv[8] = {b0.x, b0.y, b0.z, b0.w, b1.x, b1.y, b1.z, b1.w};
#pragma unroll
            for (int i = 0; i < 8; i++)
#pragma unroll
                for (int j = 0; j < 8; j++)
                    acc[i][j] += av[i] * bv[j];
        }
        __syncthreads();
    }

#pragma unroll
    for (int ii = 0; ii < 2; ii++)
#pragma unroll
    for (int i = 0; i < 4; i++) {
        int row = bm + ii * 64 + ty * 4 + i;
#pragma unroll
        for (int jj = 0; jj < 2; jj++) {
            int col = bn + jj * 64 + tx * 4;
            float4 o;
            o.x = (acc[ii * 4 + i][jj * 4 + 0] + bias[col + 0]) * scale;
            o.y = (acc[ii * 4 + i][jj * 4 + 1] + bias[col + 1]) * scale;
            o.z = (acc[ii * 4 + i][jj * 4 + 2] + bias[col + 2]) * scale;
            o.w = (acc[ii * 4 + i][jj * 4 + 3] + bias[col + 3]) * scale;
            *(float4*)&C[(size_t)row * N + col] = o;
        }
    }
}

// ---------------------------------------------------------------------------
// Scores: per (b,h), S[128 t x 128 s] = Q_h @ K_h^T  (raw, no mask)
// Full K=64 in smem (dynamic 64KB). grid = (S/128, T/128, B*H).
// ---------------------------------------------------------------------------
__global__ __launch_bounds__(256) void scores_kernel(
    const float* __restrict__ Q, const float* __restrict__ Kp,
    float* __restrict__ P)
{
    extern __shared__ float smem[];
    float* Qs = smem;              // [d][t] 64x128
    float* Ks = smem + 64 * 128;   // [d][s] 64x128

    int bh = blockIdx.z;
    int b = bh >> 3;
    int h = bh & 7;
    int t0 = blockIdx.y * 128;
    int s0 = blockIdx.x * 128;
    int tid = threadIdx.x;
    int tx = tid & 15, ty = tid >> 4;

    const float* Qb = Q + (size_t)b * TN_ * EN_ + (size_t)h * DH_;
    const float* Kb = Kp + (size_t)b * SN_ * EN_ + (size_t)h * DH_;

#pragma unroll
    for (int i = 0; i < 8; i++) {
        int f = tid + i * 256;
        int r = f >> 4;          // 0..127
        int c = (f & 15) * 4;    // 0..60
        float4 q = *(const float4*)&Qb[(size_t)(t0 + r) * EN_ + c];
        Qs[(c + 0) * 128 + r] = q.x; Qs[(c + 1) * 128 + r] = q.y;
        Qs[(c + 2) * 128 + r] = q.z; Qs[(c + 3) * 128 + r] = q.w;
        float4 k = *(const float4*)&Kb[(size_t)(s0 + r) * EN_ + c];
        Ks[(c + 0) * 128 + r] = k.x; Ks[(c + 1) * 128 + r] = k.y;
        Ks[(c + 2) * 128 + r] = k.z; Ks[(c + 3) * 128 + r] = k.w;
    }
    __syncthreads();

    float acc[8][8] = {};
#pragma unroll 4
    for (int k = 0; k < DH_; k++) {
        float4 a0 = *(float4*)&Qs[k * 128 + ty * 4];
        float4 a1 = *(float4*)&Qs[k * 128 + 64 + ty * 4];
        float4 b0 = *(float4*)&Ks[k * 128 + tx * 4];
        float4 b1 = *(float4*)&Ks[k * 128 + 64 + tx * 4];
        float av[8] = {a0.x, a0.y, a0.z, a0.w, a1.x, a1.y, a1.z, a1.w};
        float bv[8] = {b0.x, b0.y, b0.z, b0.w, b1.x, b1.y, b1.z, b1.w};
#pragma unroll
        for (int i = 0; i < 8; i++)
#pragma unroll
            for (int j = 0; j < 8; j++)
                acc[i][j] += av[i] * bv[j];
    }

    float* Pb = P + (size_t)bh * TN_ * SN_;
#pragma unroll
    for (int ii = 0; ii < 2; ii++)
#pragma unroll
    for (int i = 0; i < 4; i++) {
        int t = t0 + ii * 64 + ty * 4 + i;
#pragma unroll
        for (int jj = 0; jj < 2; jj++) {
            int s = s0 + jj * 64 + tx * 4;
            float4 o;
            o.x = acc[ii * 4 + i][jj * 4 + 0];
            o.y = acc[ii * 4 + i][jj * 4 + 1];
            o.z = acc[ii * 4 + i][jj * 4 + 2];
            o.w = acc[ii * 4 + i][jj * 4 + 3];
            *(float4*)&Pb[(size_t)t * SN_ + s] = o;
        }
    }
}

// ---------------------------------------------------------------------------
// Softmax with fused masks. One block (256 threads) per row of 2048.
// ---------------------------------------------------------------------------
__global__ __launch_bounds__(256) void softmax_kernel(
    float* __restrict__ P,
    const unsigned char* __restrict__ attn_mask,
    const unsigned char* __restrict__ kpm)
{
    size_t row = blockIdx.x;
    int bh = (int)(row >> 11);
    int t = (int)(row & 2047);
    int b = bh >> 3;

    float* p = P + row * (size_t)SN_;
    int tid = threadIdx.x;
    int lane = tid & 31, wid = tid >> 5;

    float4 v0 = *(float4*)&p[tid * 8];
    float4 v1 = *(float4*)&p[tid * 8 + 4];
    float vals[8] = {v0.x, v0.y, v0.z, v0.w, v1.x, v1.y, v1.z, v1.w};

    // masks: 8 bytes per thread from each mask
    uint2 am = *(const uint2*)&attn_mask[(size_t)t * SN_ + tid * 8];
    uint2 kp = *(const uint2*)&kpm[(size_t)b * SN_ + tid * 8];
    unsigned m0 = am.x | kp.x;
    unsigned m1 = am.y | kp.y;
#pragma unroll
    for (int i = 0; i < 4; i++) {
        if ((m0 >> (8 * i)) & 255u) vals[i] = -1e30f;
        if ((m1 >> (8 * i)) & 255u) vals[4 + i] = -1e30f;
    }

    __shared__ float sm[8];

    float mx = vals[0];
#pragma unroll
    for (int i = 1; i < 8; i++) mx = fmaxf(mx, vals[i]);
#pragma unroll
    for (int o = 16; o > 0; o >>= 1)
        mx = fmaxf(mx, __shfl_xor_sync(0xFFFFFFFFu, mx, o));
    if (lane == 0) sm[wid] = mx;
    __syncthreads();
    float rmax = sm[0];
#pragma unroll
    for (int i = 1; i < 8; i++) rmax = fmaxf(rmax, sm[i]);
    __syncthreads();

    float s = 0.f;
#pragma unroll
    for (int i = 0; i < 8; i++) {
        vals[i] = __expf(vals[i] - rmax);
        s += vals[i];
    }
#pragma unroll
    for (int o = 16; o > 0; o >>= 1)
        s += __shfl_xor_sync(0xFFFFFFFFu, s, o);
    if (lane == 0) sm[wid] = s;
    __syncthreads();
    float rsum = 0.f;
#pragma unroll
    for (int i = 0; i < 8; i++) rsum += sm[i];
    float inv = 1.0f / rsum;

    *(float4*)&p[tid * 8]     = make_float4(vals[0]*inv, vals[1]*inv, vals[2]*inv, vals[3]*inv);
    *(float4*)&p[tid * 8 + 4] = make_float4(vals[4]*inv, vals[5]*inv, vals[6]*inv, vals[7]*inv);
}

// ---------------------------------------------------------------------------
// PV: per (b,h), Ctx[128 t x 64 d] = P[128, 2048] @ V_h[2048, 64]
// BK=32, 256 threads, 8x4 microtile. grid = (T/128, B*H)
// ---------------------------------------------------------------------------
__global__ __launch_bounds__(256) void pv_kernel(
    const float* __restrict__ P, const float* __restrict__ V,
    float* __restrict__ Ctx)
{
    const int BK = 32;
    __shared__ float Ps[BK * 128];   // [s][t]
    __shared__ float Vs[BK * 64];    // [s][d]

    int bh = blockIdx.y;
    int b = bh >> 3;
    int h = bh & 7;
    int t0 = blockIdx.x * 128;
    int tid = threadIdx.x;
    int tx = tid & 15, ty = tid >> 4;

    const float* Pb = P + ((size_t)bh * TN_ + t0) * SN_;
    const float* Vb = V + (size_t)b * SN_ * EN_ + (size_t)h * DH_;

    float acc[8][4] = {};

    for (int k0 = 0; k0 < SN_; k0 += BK) {
#pragma unroll
        for (int i = 0; i < 4; i++) {
            int f = tid + i * 256;
            int r = f >> 3;          // 0..127 (t)
            int c = (f & 7) * 4;     // 0..28  (s)
            float4 v = *(const float4*)&Pb[(size_t)r * SN_ + k0 + c];
            Ps[(c + 0) * 128 + r] = v.x; Ps[(c + 1) * 128 + r] = v.y;
            Ps[(c + 2) * 128 + r] = v.z; Ps[(c + 3) * 128 + r] = v.w;
        }
#pragma unroll
        for (int i = 0; i < 2; i++) {
            int f = tid + i * 256;
            int r = f >> 4;          // 0..31 (s)
            int c = (f & 15) * 4;    // 0..60 (d)
            *(float4*)&Vs[r * 64 + c] = *(const float4*)&Vb[(size_t)(k0 + r) * EN_ + c];
        }
        __syncthreads();

#pragma unroll 4
        for (int k = 0; k < BK; k++) {
            float4 a0 = *(float4*)&Ps[k * 128 + ty * 4];
            float4 a1 = *(float4*)&Ps[k * 128 + 64 + ty * 4];
            float4 b0 = *(float4*)&Vs[k * 64 + tx * 4];
            float av[8] = {a0.x, a0.y, a0.z, a0.w, a1.x, a1.y, a1.z, a1.w};
            float bv[4] = {b0.x, b0.y, b0.z, b0.w};
#pragma unroll
            for (int i = 0; i < 8; i++)
#pragma unroll
                for (int j = 0; j < 4; j++)
                    acc[i][j] += av[i] * bv[j];
        }
        __syncthreads();
    }

#pragma unroll
    for (int ii = 0; ii < 2; ii++)
#pragma unroll
    for (int i = 0; i < 4; i++) {
        int t = t0 + ii * 64 + ty * 4 + i;
        int d = tx * 4;
        float4 o;
        o.x = acc[ii * 4 + i][0]; o.y = acc[ii * 4 + i][1];
        o.z = acc[ii * 4 + i][2]; o.w = acc[ii * 4 + i][3];
        *(float4*)&Ctx[(size_t)b * TN_ * EN_ + (size_t)t * EN_ + (size_t)h * DH_ + d] = o;
    }
}

// ---------------------------------------------------------------------------
extern "C" void kernel_launch(void* const* d_in, const int* in_sizes, int n_in,
                              void* d_out, int out_size)
{
    const float* query = (const float*)d_in[0];
    const float* key   = (const float*)d_in[1];
    const float* value = (const float*)d_in[2];
    const unsigned char* kpm       = (const unsigned char*)d_in[3];
    const unsigned char* attn_mask = (const unsigned char*)d_in[4];
    const float* Wq = (const float*)d_in[5];
    const float* bq = (const float*)d_in[6];
    const float* Wk = (const float*)d_in[7];
    const float* bk = (const float*)d_in[8];
    const float* Wv = (const float*)d_in[9];
    const float* bv = (const float*)d_in[10];
    const float* Wo = (const float*)d_in[11];
    const float* bo = (const float*)d_in[12];

    float* out = (float*)d_out;

    float *Qp, *Kp, *Vp, *Ctx, *Pfb;
    cudaGetSymbolAddress((void**)&Qp,  g_Q);
    cudaGetSymbolAddress((void**)&Kp,  g_K);
    cudaGetSymbolAddress((void**)&Vp,  g_V);
    cudaGetSymbolAddress((void**)&Ctx, g_CTX);
    cudaGetSymbolAddress((void**)&Pfb, g_P);

    float* P = ((size_t)out_size >= OUT0_ELEMS + P_ELEMS) ? (out + OUT0_ELEMS) : Pfb;

    dim3 blk(256);
    dim3 gProj(EN_ / 128, MPROJ / 128);   // (4, 64)

    const float scaling = 0.125f;

    gemm_bias_kernel<<<gProj, blk>>>(query, Wq, bq, Qp, MPROJ, EN_, EN_, scaling);
    gemm_bias_kernel<<<gProj, blk>>>(key,   Wk, bk, Kp, MPROJ, EN_, EN_, 1.0f);
    gemm_bias_kernel<<<gProj, blk>>>(value, Wv, bv, Vp, MPROJ, EN_, EN_, 1.0f);

    cudaFuncSetAttribute(scores_kernel, cudaFuncAttributeMaxDynamicSharedMemorySize, 65536);
    dim3 gScores(SN_ / 128, TN_ / 128, BN_ * HN_);   // (16, 16, 32)
    scores_kernel<<<gScores, blk, 65536>>>(Qp, Kp, P);

    softmax_kernel<<<(unsigned)((size_t)BN_ * HN_ * TN_), blk>>>(P, attn_mask, kpm);

    dim3 gPV(TN_ / 128, BN_ * HN_);                  // (16, 32)
    pv_kernel<<<gPV, blk>>>(P, Vp, Ctx);

    gemm_bias_kernel<<<gProj, blk>>>(Ctx, Wo, bo, out, MPROJ, EN_, EN_, 1.0f);
}

// round 3
// speedup vs baseline: 2.6694x; 2.1370x over previous
#include <cuda_runtime.h>
#include <cstdint>
#include <cstddef>

#define BN_ 4
#define TN_ 2048
#define SN_ 2048
#define EN_ 512
#define HN_ 8
#define DH_ 64
#define MPROJ (BN_ * TN_)
#define OUT0_ELEMS ((size_t)BN_ * TN_ * EN_)
#define P_ELEMS    ((size_t)BN_ * HN_ * TN_ * SN_)

__device__ float g_Q[(size_t)MPROJ * EN_];
__device__ float g_K[(size_t)MPROJ * EN_];
__device__ float g_V[(size_t)MPROJ * EN_];
__device__ float g_CTX[(size_t)MPROJ * EN_];
__device__ float g_P[P_ELEMS];

__device__ __forceinline__ uint32_t f2tf32(float x) {
    uint32_t r;
    asm("cvt.rna.tf32.f32 %0, %1;" : "=r"(r) : "f"(x));
    return r;
}

__device__ __forceinline__ void mma_tf32(
    float& d0, float& d1, float& d2, float& d3,
    uint32_t a0, uint32_t a1, uint32_t a2, uint32_t a3,
    uint32_t b0, uint32_t b1)
{
    asm volatile(
        "mma.sync.aligned.m16n8k8.row.col.f32.tf32.tf32.f32 "
        "{%0,%1,%2,%3}, {%4,%5,%6,%7}, {%8,%9}, {%0,%1,%2,%3};"
        : "+f"(d0), "+f"(d1), "+f"(d2), "+f"(d3)
        : "r"(a0), "r"(a1), "r"(a2), "r"(a3), "r"(b0), "r"(b1));
}

// ---------------------------------------------------------------------------
// Scores: per (b,h), S[128 t x 128 s] = Q_h @ K_h^T  (raw, tf32 mma)
// 8 warps, warp tile 64x32 (4 m-tiles x 4 n-tiles). K=64 fully in smem.
// Qs/Ks layout: [row][k], row stride 68 (4g+t conflict-free).
// ---------------------------------------------------------------------------
__global__ __launch_bounds__(256) void scores_kernel(
    const float* __restrict__ Q, const float* __restrict__ Kp,
    float* __restrict__ P)
{
    extern __shared__ uint32_t smem_u[];
    uint32_t* Qs = smem_u;               // 128 * 68
    uint32_t* Ks = smem_u + 128 * 68;    // 128 * 68

    int bh = blockIdx.z;
    int b = bh >> 3;
    int h = bh & 7;
    int t0 = blockIdx.y * 128;
    int s0 = blockIdx.x * 128;
    int tid = threadIdx.x;
    int warp = tid >> 5, lane = tid & 31;
    int g = lane >> 2, t = lane & 3;
    int wm = (warp >> 2) * 64;   // 0 or 64
    int wn = (warp & 3) * 32;    // 0..96

    const float* Qb = Q + (size_t)b * TN_ * EN_ + (size_t)h * DH_;
    const float* Kb = Kp + (size_t)b * SN_ * EN_ + (size_t)h * DH_;

#pragma unroll
    for (int i = 0; i < 8; i++) {
        int f = tid + i * 256;
        int r = f >> 4;          // 0..127
        int c = (f & 15) * 4;    // 0..60
        float4 q = *(const float4*)&Qb[(size_t)(t0 + r) * EN_ + c];
        Qs[r * 68 + c + 0] = f2tf32(q.x); Qs[r * 68 + c + 1] = f2tf32(q.y);
        Qs[r * 68 + c + 2] = f2tf32(q.z); Qs[r * 68 + c + 3] = f2tf32(q.w);
        float4 k = *(const float4*)&Kb[(size_t)(s0 + r) * EN_ + c];
        Ks[r * 68 + c + 0] = f2tf32(k.x); Ks[r * 68 + c + 1] = f2tf32(k.y);
        Ks[r * 68 + c + 2] = f2tf32(k.z); Ks[r * 68 + c + 3] = f2tf32(k.w);
    }
    __syncthreads();

    float acc[4][4][4] = {};   // [m-tile][n-tile][c0..c3]

#pragma unroll
    for (int kk = 0; kk < 64; kk += 8) {
        uint32_t a[4][4];
#pragma unroll
        for (int i = 0; i < 4; i++) {
            int base = (wm + 16 * i + g) * 68 + kk + t;
            a[i][0] = Qs[base];
            a[i][1] = Qs[base + 8 * 68];
            a[i][2] = Qs[base + 4];
            a[i][3] = Qs[base + 8 * 68 + 4];
        }
        uint32_t bf[4][2];
#pragma unroll
        for (int j = 0; j < 4; j++) {
            int base = (wn + 8 * j + g) * 68 + kk + t;
            bf[j][0] = Ks[base];
            bf[j][1] = Ks[base + 4];
        }
#pragma unroll
        for (int i = 0; i < 4; i++)
#pragma unroll
            for (int j = 0; j < 4; j++)
                mma_tf32(acc[i][j][0], acc[i][j][1], acc[i][j][2], acc[i][j][3],
                         a[i][0], a[i][1], a[i][2], a[i][3], bf[j][0], bf[j][1]);
    }

    float* Pb = P + (size_t)bh * TN_ * SN_;
#pragma unroll
    for (int i = 0; i < 4; i++) {
        int r0 = t0 + wm + 16 * i + g;
        int r1 = r0 + 8;
#pragma unroll
        for (int j = 0; j < 4; j++) {
            int c = s0 + wn + 8 * j + 2 * t;
            *(float2*)&Pb[(size_t)r0 * SN_ + c] = make_float2(acc[i][j][0], acc[i][j][1]);
            *(float2*)&Pb[(size_t)r1 * SN_ + c] = make_float2(acc[i][j][2], acc[i][j][3]);
        }
    }
}

// ---------------------------------------------------------------------------
// Projection GEMM (tf32 mma): C[M,N] = (A @ W + b) * scale
// Block 128x128, BK=16, 8 warps (warp tile 64x32).
// As: [m][k] stride 20;  Ws: [k][n] stride 136.
// ---------------------------------------------------------------------------
__global__ __launch_bounds__(256) void gemm_bias_kernel(
    const float* __restrict__ A, const float* __restrict__ W,
    const float* __restrict__ bias, float* __restrict__ C,
    int M, int N, int K, float scale)
{
    __shared__ uint32_t As[128 * 20];
    __shared__ uint32_t Ws[16 * 136];

    int tid = threadIdx.x;
    int warp = tid >> 5, lane = tid & 31;
    int g = lane >> 2, t = lane & 3;
    int wm = (warp >> 2) * 64;
    int wn = (warp & 3) * 32;
    int bm = blockIdx.y * 128, bn = blockIdx.x * 128;

    float acc[4][4][4] = {};

    for (int k0 = 0; k0 < K; k0 += 16) {
#pragma unroll
        for (int i = 0; i < 2; i++) {
            int f = tid + i * 256;
            int r = f >> 2;            // 0..127
            int c = (f & 3) * 4;       // 0,4,8,12
            float4 v = *(const float4*)&A[(size_t)(bm + r) * K + k0 + c];
            As[r * 20 + c + 0] = f2tf32(v.x); As[r * 20 + c + 1] = f2tf32(v.y);
            As[r * 20 + c + 2] = f2tf32(v.z); As[r * 20 + c + 3] = f2tf32(v.w);
        }
#pragma unroll
        for (int i = 0; i < 2; i++) {
            int f = tid + i * 256;
            int r = f >> 5;            // 0..15
            int c = (f & 31) * 4;      // 0..124
            float4 v = *(const float4*)&W[(size_t)(k0 + r) * N + bn + c];
            Ws[r * 136 + c + 0] = f2tf32(v.x); Ws[r * 136 + c + 1] = f2tf32(v.y);
            Ws[r * 136 + c + 2] = f2tf32(v.z); Ws[r * 136 + c + 3] = f2tf32(v.w);
        }
        __syncthreads();

#pragma unroll
        for (int kk = 0; kk < 16; kk += 8) {
            uint32_t a[4][4];
#pragma unroll
            for (int i = 0; i < 4; i++) {
                int base = (wm + 16 * i + g) * 20 + kk + t;
                a[i][0] = As[base];
                a[i][1] = As[base + 8 * 20];
                a[i][2] = As[base + 4];
                a[i][3] = As[base + 8 * 20 + 4];
            }
            uint32_t bf[4][2];
#pragma unroll
            for (int j = 0; j < 4; j++) {
                int col = wn + 8 * j + g;
                bf[j][0] = Ws[(kk + t) * 136 + col];
                bf[j][1] = Ws[(kk + t + 4) * 136 + col];
            }
#pragma unroll
            for (int i = 0; i < 4; i++)
#pragma unroll
                for (int j = 0; j < 4; j++)
                    mma_tf32(acc[i][j][0], acc[i][j][1], acc[i][j][2], acc[i][j][3],
                             a[i][0], a[i][1], a[i][2], a[i][3], bf[j][0], bf[j][1]);
        }
        __syncthreads();
    }

#pragma unroll
    for (int i = 0; i < 4; i++) {
        int r0 = bm + wm + 16 * i + g;
        int r1 = r0 + 8;
#pragma unroll
        for (int j = 0; j < 4; j++) {
            int c = bn + wn + 8 * j + 2 * t;
            float b0 = bias[c], b1 = bias[c + 1];
            *(float2*)&C[(size_t)r0 * N + c] =
                make_float2((acc[i][j][0] + b0) * scale, (acc[i][j][1] + b1) * scale);
            *(float2*)&C[(size_t)r1 * N + c] =
                make_float2((acc[i][j][2] + b0) * scale, (acc[i][j][3] + b1) * scale);
        }
    }
}

// ---------------------------------------------------------------------------
// Softmax with fused masks. One block (256 threads) per row of 2048.
// ---------------------------------------------------------------------------
__global__ __launch_bounds__(256) void softmax_kernel(
    float* __restrict__ P,
    const unsigned char* __restrict__ attn_mask,
    const unsigned char* __restrict__ kpm)
{
    size_t row = blockIdx.x;
    int bh = (int)(row >> 11);
    int t = (int)(row & 2047);
    int b = bh >> 3;

    float* p = P + row * (size_t)SN_;
    int tid = threadIdx.x;
    int lane = tid & 31, wid = tid >> 5;

    float4 v0 = *(float4*)&p[tid * 8];
    float4 v1 = *(float4*)&p[tid * 8 + 4];
    float vals[8] = {v0.x, v0.y, v0.z, v0.w, v1.x, v1.y, v1.z, v1.w};

    uint2 am = *(const uint2*)&attn_mask[(size_t)t * SN_ + tid * 8];
    uint2 kp = *(const uint2*)&kpm[(size_t)b * SN_ + tid * 8];
    unsigned m0 = am.x | kp.x;
    unsigned m1 = am.y | kp.y;
#pragma unroll
    for (int i = 0; i < 4; i++) {
        if ((m0 >> (8 * i)) & 255u) vals[i] = -1e30f;
        if ((m1 >> (8 * i)) & 255u) vals[4 + i] = -1e30f;
    }

    __shared__ float sm[8];

    float mx = vals[0];
#pragma unroll
    for (int i = 1; i < 8; i++) mx = fmaxf(mx, vals[i]);
#pragma unroll
    for (int o = 16; o > 0; o >>= 1)
        mx = fmaxf(mx, __shfl_xor_sync(0xFFFFFFFFu, mx, o));
    if (lane == 0) sm[wid] = mx;
    __syncthreads();
    float rmax = sm[0];
#pragma unroll
    for (int i = 1; i < 8; i++) rmax = fmaxf(rmax, sm[i]);
    __syncthreads();

    float s = 0.f;
#pragma unroll
    for (int i = 0; i < 8; i++) {
        vals[i] = __expf(vals[i] - rmax);
        s += vals[i];
    }
#pragma unroll
    for (int o = 16; o > 0; o >>= 1)
        s += __shfl_xor_sync(0xFFFFFFFFu, s, o);
    if (lane == 0) sm[wid] = s;
    __syncthreads();
    float rsum = 0.f;
#pragma unroll
    for (int i = 0; i < 8; i++) rsum += sm[i];
    float inv = 1.0f / rsum;

    *(float4*)&p[tid * 8]     = make_float4(vals[0]*inv, vals[1]*inv, vals[2]*inv, vals[3]*inv);
    *(float4*)&p[tid * 8 + 4] = make_float4(vals[4]*inv, vals[5]*inv, vals[6]*inv, vals[7]*inv);
}

// ---------------------------------------------------------------------------
// PV (tf32 mma): Ctx[128 t x 64 d] = P[128,2048] @ V_h[2048,64]
// 8 warps (4m x 2n), warp tile 32x32 (2 m-tiles x 4 n-tiles). BK=32.
// Ps: [m][k] stride 36;  Vs: [k][n] stride 72.
// ---------------------------------------------------------------------------
__global__ __launch_bounds__(256) void pv_kernel(
    const float* __restrict__ P, const float* __restrict__ V,
    float* __restrict__ Ctx)
{
    __shared__ uint32_t Ps[128 * 36];
    __shared__ uint32_t Vs[32 * 72];

    int bh = blockIdx.y;
    int b = bh >> 3;
    int h = bh & 7;
    int t0 = blockIdx.x * 128;
    int tid = threadIdx.x;
    int warp = tid >> 5, lane = tid & 31;
    int g = lane >> 2, t = lane & 3;
    int wm = (warp >> 1) * 32;   // 0,32,64,96
    int wn = (warp & 1) * 32;    // 0,32

    const float* Pb = P + ((size_t)bh * TN_ + t0) * SN_;
    const float* Vb = V + (size_t)b * SN_ * EN_ + (size_t)h * DH_;

    float acc[2][4][4] = {};

    for (int k0 = 0; k0 < SN_; k0 += 32) {
#pragma unroll
        for (int i = 0; i < 4; i++) {
            int f = tid + i * 256;
            int r = f >> 3;          // 0..127
            int c = (f & 7) * 4;     // 0..28
            float4 v = *(const float4*)&Pb[(size_t)r * SN_ + k0 + c];
            Ps[r * 36 + c + 0] = f2tf32(v.x); Ps[r * 36 + c + 1] = f2tf32(v.y);
            Ps[r * 36 + c + 2] = f2tf32(v.z); Ps[r * 36 + c + 3] = f2tf32(v.w);
        }
#pragma unroll
        for (int i = 0; i < 2; i++) {
            int f = tid + i * 256;
            int r = f >> 4;          // 0..31
            int c = (f & 15) * 4;    // 0..60
            float4 v = *(const float4*)&Vb[(size_t)(k0 + r) * EN_ + c];
            Vs[r * 72 + c + 0] = f2tf32(v.x); Vs[r * 72 + c + 1] = f2tf32(v.y);
            Vs[r * 72 + c + 2] = f2tf32(v.z); Vs[r * 72 + c + 3] = f2tf32(v.w);
        }
        __syncthreads();

#pragma unroll
        for (int kk = 0; kk < 32; kk += 8) {
            uint32_t a[2][4];
#pragma unroll
            for (int i = 0; i < 2; i++) {
                int base = (wm + 16 * i + g) * 36 + kk + t;
                a[i][0] = Ps[base];
                a[i][1] = Ps[base + 8 * 36];
                a[i][2] = Ps[base + 4];
                a[i][3] = Ps[base + 8 * 36 + 4];
            }
            uint32_t bf[4][2];
#pragma unroll
            for (int j = 0; j < 4; j++) {
                int col = wn + 8 * j + g;
                bf[j][0] = Vs[(kk + t) * 72 + col];
                bf[j][1] = Vs[(kk + t + 4) * 72 + col];
            }
#pragma unroll
            for (int i = 0; i < 2; i++)
#pragma unroll
                for (int j = 0; j < 4; j++)
                    mma_tf32(acc[i][j][0], acc[i][j][1], acc[i][j][2], acc[i][j][3],
                             a[i][0], a[i][1], a[i][2], a[i][3], bf[j][0], bf[j][1]);
        }
        __syncthreads();
    }

#pragma unroll
    for (int i = 0; i < 2; i++) {
        int r0 = t0 + wm + 16 * i + g;
        int r1 = r0 + 8;
#pragma unroll
        for (int j = 0; j < 4; j++) {
            int d = wn + 8 * j + 2 * t;
            size_t o0 = (size_t)b * TN_ * EN_ + (size_t)r0 * EN_ + (size_t)h * DH_ + d;
            size_t o1 = (size_t)b * TN_ * EN_ + (size_t)r1 * EN_ + (size_t)h * DH_ + d;
            *(float2*)&Ctx[o0] = make_float2(acc[i][j][0], acc[i][j][1]);
            *(float2*)&Ctx[o1] = make_float2(acc[i][j][2], acc[i][j][3]);
        }
    }
}

// ---------------------------------------------------------------------------
extern "C" void kernel_launch(void* const* d_in, const int* in_sizes, int n_in,
                              void* d_out, int out_size)
{
    const float* query = (const float*)d_in[0];
    const float* key   = (const float*)d_in[1];
    const float* value = (const float*)d_in[2];
    const unsigned char* kpm       = (const unsigned char*)d_in[3];
    const unsigned char* attn_mask = (const unsigned char*)d_in[4];
    const float* Wq = (const float*)d_in[5];
    const float* bq = (const float*)d_in[6];
    const float* Wk = (const float*)d_in[7];
    const float* bk = (const float*)d_in[8];
    const float* Wv = (const float*)d_in[9];
    const float* bv = (const float*)d_in[10];
    const float* Wo = (const float*)d_in[11];
    const float* bo = (const float*)d_in[12];

    float* out = (float*)d_out;

    float *Qp, *Kp, *Vp, *Ctx, *Pfb;
    cudaGetSymbolAddress((void**)&Qp,  g_Q);
    cudaGetSymbolAddress((void**)&Kp,  g_K);
    cudaGetSymbolAddress((void**)&Vp,  g_V);
    cudaGetSymbolAddress((void**)&Ctx, g_CTX);
    cudaGetSymbolAddress((void**)&Pfb, g_P);

    float* P = ((size_t)out_size >= OUT0_ELEMS + P_ELEMS) ? (out + OUT0_ELEMS) : Pfb;

    dim3 blk(256);
    dim3 gProj(EN_ / 128, MPROJ / 128);   // (4, 64)

    const float scaling = 0.125f;

    gemm_bias_kernel<<<gProj, blk>>>(query, Wq, bq, Qp, MPROJ, EN_, EN_, scaling);
    gemm_bias_kernel<<<gProj, blk>>>(key,   Wk, bk, Kp, MPROJ, EN_, EN_, 1.0f);
    gemm_bias_kernel<<<gProj, blk>>>(value, Wv, bv, Vp, MPROJ, EN_, EN_, 1.0f);

    static int smem_set = 0;
    if (!smem_set) {
        cudaFuncSetAttribute(scores_kernel, cudaFuncAttributeMaxDynamicSharedMemorySize,
                             2 * 128 * 68 * 4);
        smem_set = 1;
    }
    dim3 gScores(SN_ / 128, TN_ / 128, BN_ * HN_);   // (16, 16, 32)
    scores_kernel<<<gScores, blk, 2 * 128 * 68 * 4>>>(Qp, Kp, P);

    softmax_kernel<<<(unsigned)((size_t)BN_ * HN_ * TN_), blk>>>(P, attn_mask, kpm);

    dim3 gPV(TN_ / 128, BN_ * HN_);                  // (16, 32)
    pv_kernel<<<gPV, blk>>>(P, Vp, Ctx);

    gemm_bias_kernel<<<gProj, blk>>>(Ctx, Wo, bo, out, MPROJ, EN_, EN_, 1.0f);
}